// round 1
// baseline (speedup 1.0000x reference)
#include <cuda_runtime.h>
#include <math.h>

#define BB 32
#define HH 32
#define WW 32
#define CC 256
#define FF 64
#define HW 1024
#define NROWS (BB*HW)   /* 32768 */

// ---- static scratch (no allocation allowed) ----
__device__ float g_emb[(size_t)NROWS*FF];      // [b*hw][64]
__device__ float g_sq[NROWS];                  // ||emb||^2
__device__ float g_sc[(size_t)NROWS*CC];       // shortcut [b*hw][256]
__device__ float g_T[NROWS];                   // Tinst
__device__ float g_L[(size_t)BB*HW*HW];        // logits -> sim -> A (in place), 134 MB

// ============================================================
// K1: emb = x @ emb_W^T + emb_b ; sq = rowsum(emb^2)
// CTA: 128 rows x 64 cols (full F), 256 threads, micro 4x8
// ============================================================
__global__ __launch_bounds__(256) void k_emb(const float* __restrict__ x,
                                             const float* __restrict__ W,
                                             const float* __restrict__ bvec) {
    __shared__ float Xs[32][132];
    __shared__ float Ws[32][68];
    int row0 = blockIdx.x * 128;
    int tid = threadIdx.x;
    int fg = tid & 7, ig = tid >> 3;       // fg 0..7, ig 0..31
    int i0 = ig * 4, f0 = fg * 8;
    float acc[4][8];
#pragma unroll
    for (int a = 0; a < 4; a++)
#pragma unroll
        for (int c = 0; c < 8; c++) acc[a][c] = 0.f;

    for (int k0 = 0; k0 < CC; k0 += 32) {
        // X tile: 128 rows x 32 k = 1024 float4
#pragma unroll
        for (int u = 0; u < 4; u++) {
            int idx = tid + u * 256;
            int r = idx >> 3, seg = idx & 7;
            float4 v = *(const float4*)&x[(size_t)(row0 + r) * CC + k0 + seg * 4];
            Xs[seg*4+0][r] = v.x; Xs[seg*4+1][r] = v.y;
            Xs[seg*4+2][r] = v.z; Xs[seg*4+3][r] = v.w;
        }
        // W tile: 64 rows x 32 k = 512 float4
#pragma unroll
        for (int u = 0; u < 2; u++) {
            int idx = tid + u * 256;
            int f = idx >> 3, seg = idx & 7;
            float4 v = *(const float4*)&W[(size_t)f * CC + k0 + seg * 4];
            Ws[seg*4+0][f] = v.x; Ws[seg*4+1][f] = v.y;
            Ws[seg*4+2][f] = v.z; Ws[seg*4+3][f] = v.w;
        }
        __syncthreads();
#pragma unroll
        for (int kk = 0; kk < 32; kk++) {
            float xf[4], wf[8];
            *(float4*)xf       = *(float4*)&Xs[kk][i0];
            *(float4*)wf       = *(float4*)&Ws[kk][f0];
            *(float4*)(wf + 4) = *(float4*)&Ws[kk][f0 + 4];
#pragma unroll
            for (int a = 0; a < 4; a++)
#pragma unroll
                for (int c = 0; c < 8; c++)
                    acc[a][c] += xf[a] * wf[c];
        }
        __syncthreads();
    }
    // epilogue: bias, write emb, sq partials
#pragma unroll
    for (int a = 0; a < 4; a++) {
        float s = 0.f;
#pragma unroll
        for (int c = 0; c < 8; c++) {
            acc[a][c] += bvec[f0 + c];
            s += acc[a][c] * acc[a][c];
        }
        *(float4*)&g_emb[(size_t)(row0 + i0 + a) * FF + f0]     = *(float4*)&acc[a][0];
        *(float4*)&g_emb[(size_t)(row0 + i0 + a) * FF + f0 + 4] = *(float4*)&acc[a][4];
        // reduce over the 8 fg-lanes (consecutive in warp)
        s += __shfl_down_sync(0xffffffffu, s, 4, 8);
        s += __shfl_down_sync(0xffffffffu, s, 2, 8);
        s += __shfl_down_sync(0xffffffffu, s, 1, 8);
        if (fg == 0) g_sq[row0 + i0 + a] = s;
    }
}

// ============================================================
// K2: shortcut = x @ attn_W^T + attn_b
// 128x128 tile, 256 threads, 8x8 micro, k-chunk 8
// ============================================================
__global__ __launch_bounds__(256) void k_shortcut(const float* __restrict__ x,
                                                  const float* __restrict__ W,
                                                  const float* __restrict__ bias) {
    __shared__ float As[8][132];
    __shared__ float Bs[8][132];
    int m0 = blockIdx.y * 128, n0 = blockIdx.x * 128;
    int tid = threadIdx.x;
    int mi = tid >> 4, ni = tid & 15;
    float acc[8][8];
#pragma unroll
    for (int p = 0; p < 8; p++)
#pragma unroll
        for (int q = 0; q < 8; q++) acc[p][q] = 0.f;

    for (int k0 = 0; k0 < CC; k0 += 8) {
        int r = tid >> 1, seg = tid & 1;
        float4 v = *(const float4*)&x[(size_t)(m0 + r) * CC + k0 + seg * 4];
        As[seg*4+0][r] = v.x; As[seg*4+1][r] = v.y;
        As[seg*4+2][r] = v.z; As[seg*4+3][r] = v.w;
        float4 w = *(const float4*)&W[(size_t)(n0 + r) * CC + k0 + seg * 4];
        Bs[seg*4+0][r] = w.x; Bs[seg*4+1][r] = w.y;
        Bs[seg*4+2][r] = w.z; Bs[seg*4+3][r] = w.w;
        __syncthreads();
#pragma unroll
        for (int kk = 0; kk < 8; kk++) {
            float a[8], b[8];
            *(float4*)a       = *(float4*)&As[kk][mi*4];
            *(float4*)(a + 4) = *(float4*)&As[kk][mi*4 + 64];
            *(float4*)b       = *(float4*)&Bs[kk][ni*4];
            *(float4*)(b + 4) = *(float4*)&Bs[kk][ni*4 + 64];
#pragma unroll
            for (int p = 0; p < 8; p++)
#pragma unroll
                for (int q = 0; q < 8; q++)
                    acc[p][q] += a[p] * b[q];
        }
        __syncthreads();
    }
#pragma unroll
    for (int p = 0; p < 8; p++) {
        int r = m0 + ((p < 4) ? (mi*4 + p) : (64 + mi*4 + p - 4));
        float o[8];
#pragma unroll
        for (int q = 0; q < 8; q++) {
            int c = (q < 4) ? (ni*4 + q) : (64 + ni*4 + q - 4);
            o[q] = acc[p][q] + bias[n0 + c];
        }
        *(float4*)&g_sc[(size_t)r * CC + n0 + ni*4]      = *(float4*)o;
        *(float4*)&g_sc[(size_t)r * CC + n0 + 64 + ni*4] = *(float4*)(o + 4);
    }
}

// ============================================================
// K2b: Tinst[r] = shortcut[r] . thr_W + thr_b  (warp per row)
// ============================================================
__global__ __launch_bounds__(256) void k_thr(const float* __restrict__ thrW,
                                             const float* __restrict__ thrb) {
    int row = blockIdx.x * 8 + (threadIdx.x >> 5);
    int lane = threadIdx.x & 31;
    const float* s = g_sc + (size_t)row * CC;
    float acc = 0.f;
#pragma unroll
    for (int u = 0; u < 2; u++) {
        float4 a = *(const float4*)&s[(u * 32 + lane) * 4];
        float4 w = *(const float4*)&thrW[(u * 32 + lane) * 4];
        acc += a.x*w.x + a.y*w.y + a.z*w.z + a.w*w.w;
    }
#pragma unroll
    for (int o = 16; o; o >>= 1) acc += __shfl_xor_sync(0xffffffffu, acc, o);
    if (lane == 0) g_T[row] = acc + thrb[0];
}

// ============================================================
// K3: logits L[b,i,j] = exp(-max(sq_i+sq_j-2*emb_i.emb_j,0)) - 1 + mask(i,j)
// 128x128 tile, 256 threads, 8x8 micro, K=64 chunk 16
// ============================================================
__global__ __launch_bounds__(256) void k_gram() {
    __shared__ float Es[16][132];
    __shared__ float Fs[16][132];
    int b = blockIdx.z;
    int i0 = blockIdx.y * 128, j0 = blockIdx.x * 128;
    const float* E = g_emb + ((size_t)b * HW) * FF;
    int tid = threadIdx.x;
    int mi = tid >> 4, ni = tid & 15;
    float acc[8][8];
#pragma unroll
    for (int p = 0; p < 8; p++)
#pragma unroll
        for (int q = 0; q < 8; q++) acc[p][q] = 0.f;

    for (int k0 = 0; k0 < FF; k0 += 16) {
#pragma unroll
        for (int u = 0; u < 2; u++) {
            int idx = tid + u * 256;         // 0..511 float4 slots: 128 rows x 4 segs
            int r = idx >> 2, seg = idx & 3;
            float4 v = *(const float4*)&E[(size_t)(i0 + r) * FF + k0 + seg * 4];
            Es[seg*4+0][r] = v.x; Es[seg*4+1][r] = v.y;
            Es[seg*4+2][r] = v.z; Es[seg*4+3][r] = v.w;
            float4 w = *(const float4*)&E[(size_t)(j0 + r) * FF + k0 + seg * 4];
            Fs[seg*4+0][r] = w.x; Fs[seg*4+1][r] = w.y;
            Fs[seg*4+2][r] = w.z; Fs[seg*4+3][r] = w.w;
        }
        __syncthreads();
#pragma unroll
        for (int kk = 0; kk < 16; kk++) {
            float a[8], c[8];
            *(float4*)a       = *(float4*)&Es[kk][mi*4];
            *(float4*)(a + 4) = *(float4*)&Es[kk][mi*4 + 64];
            *(float4*)c       = *(float4*)&Fs[kk][ni*4];
            *(float4*)(c + 4) = *(float4*)&Fs[kk][ni*4 + 64];
#pragma unroll
            for (int p = 0; p < 8; p++)
#pragma unroll
                for (int q = 0; q < 8; q++)
                    acc[p][q] += a[p] * c[q];
        }
        __syncthreads();
    }
    const float* sqb = g_sq + b * HW;
#pragma unroll
    for (int p = 0; p < 8; p++) {
        int gi = i0 + ((p < 4) ? (mi*4 + p) : (64 + mi*4 + p - 4));
        float si = sqb[gi];
        int yi = gi >> 5, xi = gi & 31;
        float o[8];
#pragma unroll
        for (int q = 0; q < 8; q++) {
            int gj = j0 + ((q < 4) ? (ni*4 + q) : (64 + ni*4 + q - 4));
            float d2 = fmaxf(si + sqb[gj] - 2.f * acc[p][q], 0.f);
            int yj = gj >> 5, xj = gj & 31;
            int diff = abs(yi - yj) + abs(xi - xj);
            float mask = (diff <= 32) ? (float)diff * (1.f / 32.f) : 0.f;
            o[q] = __expf(-d2) - 1.f + mask;
        }
        size_t base = ((size_t)b * HW + gi) * HW;
        *(float4*)&g_L[base + j0 + ni*4]      = *(float4*)o;
        *(float4*)&g_L[base + j0 + 64 + ni*4] = *(float4*)(o + 4);
    }
}

// ============================================================
// K4: row-wise sim=softmax(L); A=softmax(relu(sim - T[j])), in place.
// warp per row, whole row (1024) in registers.
// ============================================================
__global__ __launch_bounds__(256) void k_softmax() {
    int row = blockIdx.x * 8 + (threadIdx.x >> 5);   // 0..32767
    int lane = threadIdx.x & 31;
    int b = row >> 10;
    float* Lrow = g_L + (size_t)row * HW;
    const float* T = g_T + b * HW;

    float v[32];
#pragma unroll
    for (int ch = 0; ch < 8; ch++) {
        float4 t = *(const float4*)&Lrow[(ch * 32 + lane) * 4];
        v[ch*4+0] = t.x; v[ch*4+1] = t.y; v[ch*4+2] = t.z; v[ch*4+3] = t.w;
    }
    // softmax #1
    float m1 = -1e30f;
#pragma unroll
    for (int i = 0; i < 32; i++) m1 = fmaxf(m1, v[i]);
#pragma unroll
    for (int o = 16; o; o >>= 1) m1 = fmaxf(m1, __shfl_xor_sync(0xffffffffu, m1, o));
    float s1 = 0.f;
#pragma unroll
    for (int i = 0; i < 32; i++) { v[i] = __expf(v[i] - m1); s1 += v[i]; }
#pragma unroll
    for (int o = 16; o; o >>= 1) s1 += __shfl_xor_sync(0xffffffffu, s1, o);
    float r1 = 1.f / s1;
    // a = relu(sim - T[j])
#pragma unroll
    for (int ch = 0; ch < 8; ch++) {
        float4 t = *(const float4*)&T[(ch * 32 + lane) * 4];
        v[ch*4+0] = fmaxf(v[ch*4+0] * r1 - t.x, 0.f);
        v[ch*4+1] = fmaxf(v[ch*4+1] * r1 - t.y, 0.f);
        v[ch*4+2] = fmaxf(v[ch*4+2] * r1 - t.z, 0.f);
        v[ch*4+3] = fmaxf(v[ch*4+3] * r1 - t.w, 0.f);
    }
    // softmax #2
    float m2 = 0.f;
#pragma unroll
    for (int i = 0; i < 32; i++) m2 = fmaxf(m2, v[i]);
#pragma unroll
    for (int o = 16; o; o >>= 1) m2 = fmaxf(m2, __shfl_xor_sync(0xffffffffu, m2, o));
    float s2 = 0.f;
#pragma unroll
    for (int i = 0; i < 32; i++) { v[i] = __expf(v[i] - m2); s2 += v[i]; }
#pragma unroll
    for (int o = 16; o; o >>= 1) s2 += __shfl_xor_sync(0xffffffffu, s2, o);
    float r2 = 1.f / s2;
#pragma unroll
    for (int ch = 0; ch < 8; ch++) {
        float4 t;
        t.x = v[ch*4+0] * r2; t.y = v[ch*4+1] * r2;
        t.z = v[ch*4+2] * r2; t.w = v[ch*4+3] * r2;
        *(float4*)&Lrow[(ch * 32 + lane) * 4] = t;
    }
}

// ============================================================
// K5: out[b,i,c] = x[b,i,c] + sum_j A[b,i,j] * shortcut[b,j,c]
// per-batch GEMM 1024x256, K=1024. 128x128 tiles, 8x8 micro, chunk 8.
// ============================================================
__global__ __launch_bounds__(256) void k_av(const float* __restrict__ x,
                                            float* __restrict__ out) {
    __shared__ float As[8][132];
    __shared__ float Bs[8][132];
    int b = blockIdx.z;
    int m0 = blockIdx.y * 128, n0 = blockIdx.x * 128;
    const float* Am = g_L + (size_t)b * HW * HW;
    const float* S  = g_sc + (size_t)b * HW * CC;
    int tid = threadIdx.x;
    int mi = tid >> 4, ni = tid & 15;
    float acc[8][8];
#pragma unroll
    for (int p = 0; p < 8; p++)
#pragma unroll
        for (int q = 0; q < 8; q++) acc[p][q] = 0.f;

    for (int k0 = 0; k0 < HW; k0 += 8) {
        {   // A: transpose load, 128 rows x 8 k
            int r = tid >> 1, seg = tid & 1;
            float4 v = *(const float4*)&Am[(size_t)(m0 + r) * HW + k0 + seg * 4];
            As[seg*4+0][r] = v.x; As[seg*4+1][r] = v.y;
            As[seg*4+2][r] = v.z; As[seg*4+3][r] = v.w;
        }
        {   // B (=shortcut): direct copy, 8 k-rows x 128 cols
            int kk = tid >> 5, c4 = tid & 31;
            float4 v = *(const float4*)&S[(size_t)(k0 + kk) * CC + n0 + c4 * 4];
            *(float4*)&Bs[kk][c4 * 4] = v;
        }
        __syncthreads();
#pragma unroll
        for (int kk = 0; kk < 8; kk++) {
            float a[8], c[8];
            *(float4*)a       = *(float4*)&As[kk][mi*4];
            *(float4*)(a + 4) = *(float4*)&As[kk][mi*4 + 64];
            *(float4*)c       = *(float4*)&Bs[kk][ni*4];
            *(float4*)(c + 4) = *(float4*)&Bs[kk][ni*4 + 64];
#pragma unroll
            for (int p = 0; p < 8; p++)
#pragma unroll
                for (int q = 0; q < 8; q++)
                    acc[p][q] += a[p] * c[q];
        }
        __syncthreads();
    }
#pragma unroll
    for (int p = 0; p < 8; p++) {
        int gi = m0 + ((p < 4) ? (mi*4 + p) : (64 + mi*4 + p - 4));
        size_t rowoff = ((size_t)b * HW + gi) * CC;
        float4 x0 = *(const float4*)&x[rowoff + n0 + ni*4];
        float4 x1 = *(const float4*)&x[rowoff + n0 + 64 + ni*4];
        float4 o0, o1;
        o0.x = acc[p][0] + x0.x; o0.y = acc[p][1] + x0.y;
        o0.z = acc[p][2] + x0.z; o0.w = acc[p][3] + x0.w;
        o1.x = acc[p][4] + x1.x; o1.y = acc[p][5] + x1.y;
        o1.z = acc[p][6] + x1.z; o1.w = acc[p][7] + x1.w;
        *(float4*)&out[rowoff + n0 + ni*4]      = o0;
        *(float4*)&out[rowoff + n0 + 64 + ni*4] = o1;
    }
}

// ============================================================
extern "C" void kernel_launch(void* const* d_in, const int* in_sizes, int n_in,
                              void* d_out, int out_size) {
    (void)in_sizes; (void)n_in; (void)out_size;
    const float* x     = (const float*)d_in[0];
    const float* embW  = (const float*)d_in[1];
    const float* embb  = (const float*)d_in[2];
    const float* attnW = (const float*)d_in[3];
    const float* attnb = (const float*)d_in[4];
    const float* thrW  = (const float*)d_in[5];
    const float* thrb  = (const float*)d_in[6];
    float* out = (float*)d_out;

    k_emb<<<NROWS / 128, 256>>>(x, embW, embb);
    k_shortcut<<<dim3(CC / 128, NROWS / 128), 256>>>(x, attnW, attnb);
    k_thr<<<NROWS / 8, 256>>>(thrW, thrb);
    k_gram<<<dim3(HW / 128, HW / 128, BB), 256>>>();
    k_softmax<<<NROWS / 8, 256>>>();
    k_av<<<dim3(CC / 128, HW / 128, BB), 256>>>(x, out);
}

// round 3
// speedup vs baseline: 1.6270x; 1.6270x over previous
#include <cuda_runtime.h>
#include <cuda_bf16.h>
#include <math.h>
#include <stdint.h>

#define BB 32
#define CC 256
#define FF 64
#define HW 1024
#define NROWS (BB*HW)   /* 32768 */

// ---- static scratch (no allocation allowed) ----
__device__ float g_sq[NROWS];                  // ||emb||^2
__device__ float g_sc[(size_t)NROWS*CC];       // shortcut [b*hw][256]
__device__ float g_T[NROWS];                   // Tinst
__device__ float g_L[(size_t)BB*HW*HW];        // logits (fp32), 134 MB
__device__ __align__(16) __nv_bfloat16 g_Ehi[(size_t)NROWS*FF];   // emb hi split
__device__ __align__(16) __nv_bfloat16 g_Elo[(size_t)NROWS*FF];   // emb lo split
__device__ __align__(16) __nv_bfloat16 g_Ahi[(size_t)BB*HW*HW];   // A hi split, 64 MB
__device__ __align__(16) __nv_bfloat16 g_Alo[(size_t)BB*HW*HW];   // A lo split, 64 MB
__device__ __align__(16) __nv_bfloat16 g_sThi[(size_t)BB*CC*HW];  // shortcut^T hi [b][c][j]
__device__ __align__(16) __nv_bfloat16 g_sTlo[(size_t)BB*CC*HW];  // shortcut^T lo

// ================= portable tensor-core helpers =================
__device__ __forceinline__ uint32_t smem_u32(const void* p) {
    uint32_t a;
    asm("{ .reg .u64 t; cvta.to.shared.u64 t, %1; cvt.u32.u64 %0, t; }" : "=r"(a) : "l"(p));
    return a;
}
#define CP_ASYNC16(dst, src) \
    asm volatile("cp.async.cg.shared.global [%0], [%1], 16;" :: "r"(dst), "l"(src) : "memory")
#define CP_COMMIT()  asm volatile("cp.async.commit_group;" ::: "memory")
#define CP_WAIT1()   asm volatile("cp.async.wait_group 1;" ::: "memory")
#define CP_WAIT0()   asm volatile("cp.async.wait_group 0;" ::: "memory")

#define LDSM_X4(r0, r1, r2, r3, addr) \
    asm volatile("ldmatrix.sync.aligned.m8n8.x4.shared.b16 {%0,%1,%2,%3}, [%4];" \
        : "=r"(r0), "=r"(r1), "=r"(r2), "=r"(r3) : "r"(addr))

#define MMA16816(d, a, b0, b1) \
    asm volatile("mma.sync.aligned.m16n8k16.row.col.f32.bf16.bf16.f32 " \
        "{%0,%1,%2,%3},{%4,%5,%6,%7},{%8,%9},{%0,%1,%2,%3};" \
        : "+f"((d)[0]), "+f"((d)[1]), "+f"((d)[2]), "+f"((d)[3]) \
        : "r"((a)[0]), "r"((a)[1]), "r"((a)[2]), "r"((a)[3]), "r"(b0), "r"(b1))

// ============================================================
// K1: emb = x @ emb_W^T + emb_b ; sq = rowsum(emb^2); emit bf16 hi/lo.
// ============================================================
__global__ __launch_bounds__(256) void k_emb(const float* __restrict__ x,
                                             const float* __restrict__ W,
                                             const float* __restrict__ bvec) {
    __shared__ float Xs[32][132];
    __shared__ float Ws[32][68];
    int row0 = blockIdx.x * 128;
    int tid = threadIdx.x;
    int fg = tid & 7, ig = tid >> 3;
    int i0 = ig * 4, f0 = fg * 8;
    float acc[4][8];
#pragma unroll
    for (int a = 0; a < 4; a++)
#pragma unroll
        for (int c = 0; c < 8; c++) acc[a][c] = 0.f;

    for (int k0 = 0; k0 < CC; k0 += 32) {
#pragma unroll
        for (int u = 0; u < 4; u++) {
            int idx = tid + u * 256;
            int r = idx >> 3, seg = idx & 7;
            float4 v = *(const float4*)&x[(size_t)(row0 + r) * CC + k0 + seg * 4];
            Xs[seg*4+0][r] = v.x; Xs[seg*4+1][r] = v.y;
            Xs[seg*4+2][r] = v.z; Xs[seg*4+3][r] = v.w;
        }
#pragma unroll
        for (int u = 0; u < 2; u++) {
            int idx = tid + u * 256;
            int f = idx >> 3, seg = idx & 7;
            float4 v = *(const float4*)&W[(size_t)f * CC + k0 + seg * 4];
            Ws[seg*4+0][f] = v.x; Ws[seg*4+1][f] = v.y;
            Ws[seg*4+2][f] = v.z; Ws[seg*4+3][f] = v.w;
        }
        __syncthreads();
#pragma unroll
        for (int kk = 0; kk < 32; kk++) {
            float xf[4], wf[8];
            *(float4*)xf       = *(float4*)&Xs[kk][i0];
            *(float4*)wf       = *(float4*)&Ws[kk][f0];
            *(float4*)(wf + 4) = *(float4*)&Ws[kk][f0 + 4];
#pragma unroll
            for (int a = 0; a < 4; a++)
#pragma unroll
                for (int c = 0; c < 8; c++)
                    acc[a][c] += xf[a] * wf[c];
        }
        __syncthreads();
    }
#pragma unroll
    for (int a = 0; a < 4; a++) {
        float s = 0.f;
        __align__(16) __nv_bfloat16 hb[8], lb[8];
#pragma unroll
        for (int c = 0; c < 8; c++) {
            acc[a][c] += bvec[f0 + c];
            s += acc[a][c] * acc[a][c];
            hb[c] = __float2bfloat16(acc[a][c]);
            lb[c] = __float2bfloat16(acc[a][c] - __bfloat162float(hb[c]));
        }
        size_t off = (size_t)(row0 + i0 + a) * FF + f0;
        *(uint4*)&g_Ehi[off] = *(uint4*)hb;
        *(uint4*)&g_Elo[off] = *(uint4*)lb;
        s += __shfl_down_sync(0xffffffffu, s, 4, 8);
        s += __shfl_down_sync(0xffffffffu, s, 2, 8);
        s += __shfl_down_sync(0xffffffffu, s, 1, 8);
        if (fg == 0) g_sq[row0 + i0 + a] = s;
    }
}

// ============================================================
// K2: shortcut = x @ attn_W^T + attn_b  (fp32 SIMT)
// ============================================================
__global__ __launch_bounds__(256) void k_shortcut(const float* __restrict__ x,
                                                  const float* __restrict__ W,
                                                  const float* __restrict__ bias) {
    __shared__ float As[8][132];
    __shared__ float Bs[8][132];
    int m0 = blockIdx.y * 128, n0 = blockIdx.x * 128;
    int tid = threadIdx.x;
    int mi = tid >> 4, ni = tid & 15;
    float acc[8][8];
#pragma unroll
    for (int p = 0; p < 8; p++)
#pragma unroll
        for (int q = 0; q < 8; q++) acc[p][q] = 0.f;

    for (int k0 = 0; k0 < CC; k0 += 8) {
        int r = tid >> 1, seg = tid & 1;
        float4 v = *(const float4*)&x[(size_t)(m0 + r) * CC + k0 + seg * 4];
        As[seg*4+0][r] = v.x; As[seg*4+1][r] = v.y;
        As[seg*4+2][r] = v.z; As[seg*4+3][r] = v.w;
        float4 w = *(const float4*)&W[(size_t)(n0 + r) * CC + k0 + seg * 4];
        Bs[seg*4+0][r] = w.x; Bs[seg*4+1][r] = w.y;
        Bs[seg*4+2][r] = w.z; Bs[seg*4+3][r] = w.w;
        __syncthreads();
#pragma unroll
        for (int kk = 0; kk < 8; kk++) {
            float a[8], b[8];
            *(float4*)a       = *(float4*)&As[kk][mi*4];
            *(float4*)(a + 4) = *(float4*)&As[kk][mi*4 + 64];
            *(float4*)b       = *(float4*)&Bs[kk][ni*4];
            *(float4*)(b + 4) = *(float4*)&Bs[kk][ni*4 + 64];
#pragma unroll
            for (int p = 0; p < 8; p++)
#pragma unroll
                for (int q = 0; q < 8; q++)
                    acc[p][q] += a[p] * b[q];
        }
        __syncthreads();
    }
#pragma unroll
    for (int p = 0; p < 8; p++) {
        int r = m0 + ((p < 4) ? (mi*4 + p) : (64 + mi*4 + p - 4));
        float o[8];
#pragma unroll
        for (int q = 0; q < 8; q++) {
            int c = (q < 4) ? (ni*4 + q) : (64 + ni*4 + q - 4);
            o[q] = acc[p][q] + bias[n0 + c];
        }
        *(float4*)&g_sc[(size_t)r * CC + n0 + ni*4]      = *(float4*)o;
        *(float4*)&g_sc[(size_t)r * CC + n0 + 64 + ni*4] = *(float4*)(o + 4);
    }
}

// ============================================================
// K2b: Tinst[r] = shortcut[r] . thr_W + thr_b
// ============================================================
__global__ __launch_bounds__(256) void k_thr(const float* __restrict__ thrW,
                                             const float* __restrict__ thrb) {
    int row = blockIdx.x * 8 + (threadIdx.x >> 5);
    int lane = threadIdx.x & 31;
    const float* s = g_sc + (size_t)row * CC;
    float acc = 0.f;
#pragma unroll
    for (int u = 0; u < 2; u++) {
        float4 a = *(const float4*)&s[(u * 32 + lane) * 4];
        float4 w = *(const float4*)&thrW[(u * 32 + lane) * 4];
        acc += a.x*w.x + a.y*w.y + a.z*w.z + a.w*w.w;
    }
#pragma unroll
    for (int o = 16; o; o >>= 1) acc += __shfl_xor_sync(0xffffffffu, acc, o);
    if (lane == 0) g_T[row] = acc + thrb[0];
}

// ============================================================
// K2c: transpose + bf16-split shortcut -> g_sT*[b][c][j]
// ============================================================
__global__ __launch_bounds__(256) void k_split() {
    __shared__ float tile[32][33];
    int b = blockIdx.z;
    int j0 = blockIdx.x * 32, c0 = blockIdx.y * 32;
    int tx = threadIdx.x & 31, ty = threadIdx.x >> 5;
#pragma unroll
    for (int q = 0; q < 4; q++) {
        int j = ty * 4 + q;
        tile[j][tx] = g_sc[((size_t)(b * HW) + j0 + j) * CC + c0 + tx];
    }
    __syncthreads();
#pragma unroll
    for (int q = 0; q < 4; q++) {
        int c = ty * 4 + q;
        float v = tile[tx][c];
        __nv_bfloat16 hi = __float2bfloat16(v);
        __nv_bfloat16 lo = __float2bfloat16(v - __bfloat162float(hi));
        size_t off = ((size_t)(b * CC) + c0 + c) * HW + j0 + tx;
        g_sThi[off] = hi;
        g_sTlo[off] = lo;
    }
}

// ============================================================
// K3: gram via mma.sync — L[b,i,j] = exp(-d2) - 1 + mask
// CTA 128x128, 8 warps (64x32 tile), K = 3 segs x 64.
// ============================================================
__global__ __launch_bounds__(256) void k_gram_mma() {
    __shared__ __align__(16) char smbuf[32768];
    uint32_t smem_base = smem_u32(smbuf);
    const int tid = threadIdx.x, lane = tid & 31, wid = tid >> 5;
    const int wm = wid >> 2, wn = wid & 3;
    const int bb = blockIdx.z, i0 = blockIdx.y * 128, j0 = blockIdx.x * 128;

    float acc[4][4][4];
#pragma unroll
    for (int a = 0; a < 4; a++)
#pragma unroll
        for (int b = 0; b < 4; b++)
#pragma unroll
            for (int c = 0; c < 4; c++) acc[a][b][c] = 0.f;

    auto issue = [&](int kc, int buf) {
        int seg = kc >> 1, f0 = (kc & 1) * 32;
        const __nv_bfloat16* Ap = (seg < 2 ? g_Ehi : g_Elo)
                                  + (size_t)(bb * HW + i0) * FF + f0;
        const __nv_bfloat16* Bp = (seg == 1 ? g_Elo : g_Ehi)
                                  + (size_t)(bb * HW + j0) * FF + f0;
        uint32_t Ab = smem_base + buf * 16384;
        uint32_t Bb = Ab + 8192;
#pragma unroll
        for (int u = 0; u < 2; u++) {
            int idx = tid + u * 256;
            int r = idx >> 2, c = idx & 3;
            uint32_t sw = (uint32_t)((c ^ ((r >> 1) & 3)) << 4);
            CP_ASYNC16(Ab + r * 64 + sw, Ap + (size_t)r * FF + c * 8);
            CP_ASYNC16(Bb + r * 64 + sw, Bp + (size_t)r * FF + c * 8);
        }
        CP_COMMIT();
    };

    const int NC = 6;
    issue(0, 0);
    for (int kc = 0; kc < NC; kc++) {
        if (kc + 1 < NC) { issue(kc + 1, (kc + 1) & 1); CP_WAIT1(); }
        else CP_WAIT0();
        __syncthreads();
        uint32_t Ab = smem_base + (kc & 1) * 16384;
        uint32_t Bb = Ab + 8192;
#pragma unroll
        for (int s = 0; s < 2; s++) {
            uint32_t afr[4][4];
#pragma unroll
            for (int mi = 0; mi < 4; mi++) {
                int r = wm * 64 + mi * 16 + (lane & 15);
                uint32_t addr = Ab + r * 64 + (((s*2 + (lane >> 4)) ^ ((r >> 1) & 3)) << 4);
                LDSM_X4(afr[mi][0], afr[mi][1], afr[mi][2], afr[mi][3], addr);
            }
            uint32_t bfr[2][4];
#pragma unroll
            for (int p = 0; p < 2; p++) {
                int nloc = p * 16 + ((lane >> 4) << 3) + (lane & 7);
                int khalf = (lane >> 3) & 1;
                int r = wn * 32 + nloc;
                uint32_t addr = Bb + r * 64 + (((s*2 + khalf) ^ ((r >> 1) & 3)) << 4);
                LDSM_X4(bfr[p][0], bfr[p][1], bfr[p][2], bfr[p][3], addr);
            }
#pragma unroll
            for (int mi = 0; mi < 4; mi++)
#pragma unroll
                for (int ni = 0; ni < 4; ni++)
                    MMA16816(acc[mi][ni], afr[mi],
                             bfr[ni >> 1][(ni & 1) * 2], bfr[ni >> 1][(ni & 1) * 2 + 1]);
        }
        __syncthreads();
    }

    // epilogue
    const float* sqb = g_sq + bb * HW;
    int r0 = i0 + wm * 64 + (lane >> 2);
    int c0 = j0 + wn * 32 + (lane & 3) * 2;
#pragma unroll
    for (int mi = 0; mi < 4; mi++) {
#pragma unroll
        for (int ni = 0; ni < 4; ni++) {
            int gc = c0 + ni * 8;
            float sj0 = sqb[gc], sj1 = sqb[gc + 1];
            int yj0 = gc >> 5, xj0 = gc & 31;
            int yj1 = (gc + 1) >> 5, xj1 = (gc + 1) & 31;
#pragma unroll
            for (int h = 0; h < 2; h++) {
                int gr = r0 + mi * 16 + h * 8;
                float si = sqb[gr];
                int yi = gr >> 5, xi = gr & 31;
                float d0 = fmaxf(si + sj0 - 2.f * acc[mi][ni][h*2+0], 0.f);
                float d1 = fmaxf(si + sj1 - 2.f * acc[mi][ni][h*2+1], 0.f);
                int df0 = abs(yi - yj0) + abs(xi - xj0);
                int df1 = abs(yi - yj1) + abs(xi - xj1);
                float m0 = (df0 <= 32) ? (float)df0 * (1.f/32.f) : 0.f;
                float m1 = (df1 <= 32) ? (float)df1 * (1.f/32.f) : 0.f;
                float2 o;
                o.x = __expf(-d0) - 1.f + m0;
                o.y = __expf(-d1) - 1.f + m1;
                *(float2*)&g_L[((size_t)bb * HW + gr) * HW + gc] = o;
            }
        }
    }
}

// ============================================================
// K4: row-wise double softmax -> A bf16 hi/lo splits. warp per row.
// ============================================================
__global__ __launch_bounds__(256) void k_softmax() {
    int row = blockIdx.x * 8 + (threadIdx.x >> 5);
    int lane = threadIdx.x & 31;
    int b = row >> 10;
    const float* Lrow = g_L + (size_t)row * HW;
    const float* T = g_T + b * HW;

    float v[32];
#pragma unroll
    for (int ch = 0; ch < 8; ch++) {
        float4 t = *(const float4*)&Lrow[(ch * 32 + lane) * 4];
        v[ch*4+0] = t.x; v[ch*4+1] = t.y; v[ch*4+2] = t.z; v[ch*4+3] = t.w;
    }
    float m1 = -1e30f;
#pragma unroll
    for (int i = 0; i < 32; i++) m1 = fmaxf(m1, v[i]);
#pragma unroll
    for (int o = 16; o; o >>= 1) m1 = fmaxf(m1, __shfl_xor_sync(0xffffffffu, m1, o));
    float s1 = 0.f;
#pragma unroll
    for (int i = 0; i < 32; i++) { v[i] = __expf(v[i] - m1); s1 += v[i]; }
#pragma unroll
    for (int o = 16; o; o >>= 1) s1 += __shfl_xor_sync(0xffffffffu, s1, o);
    float r1 = 1.f / s1;
#pragma unroll
    for (int ch = 0; ch < 8; ch++) {
        float4 t = *(const float4*)&T[(ch * 32 + lane) * 4];
        v[ch*4+0] = fmaxf(v[ch*4+0] * r1 - t.x, 0.f);
        v[ch*4+1] = fmaxf(v[ch*4+1] * r1 - t.y, 0.f);
        v[ch*4+2] = fmaxf(v[ch*4+2] * r1 - t.z, 0.f);
        v[ch*4+3] = fmaxf(v[ch*4+3] * r1 - t.w, 0.f);
    }
    float m2 = 0.f;
#pragma unroll
    for (int i = 0; i < 32; i++) m2 = fmaxf(m2, v[i]);
#pragma unroll
    for (int o = 16; o; o >>= 1) m2 = fmaxf(m2, __shfl_xor_sync(0xffffffffu, m2, o));
    float s2 = 0.f;
#pragma unroll
    for (int i = 0; i < 32; i++) { v[i] = __expf(v[i] - m2); s2 += v[i]; }
#pragma unroll
    for (int o = 16; o; o >>= 1) s2 += __shfl_xor_sync(0xffffffffu, s2, o);
    float r2 = 1.f / s2;
    __nv_bfloat16* Ah = g_Ahi + (size_t)row * HW;
    __nv_bfloat16* Al = g_Alo + (size_t)row * HW;
#pragma unroll
    for (int ch = 0; ch < 8; ch++) {
        int j = (ch * 32 + lane) * 4;
        float f0 = v[ch*4+0] * r2, f1 = v[ch*4+1] * r2;
        float f2 = v[ch*4+2] * r2, f3 = v[ch*4+3] * r2;
        __nv_bfloat162 h01, h23, l01, l23;
        h01.x = __float2bfloat16(f0); h01.y = __float2bfloat16(f1);
        h23.x = __float2bfloat16(f2); h23.y = __float2bfloat16(f3);
        l01.x = __float2bfloat16(f0 - __bfloat162float(h01.x));
        l01.y = __float2bfloat16(f1 - __bfloat162float(h01.y));
        l23.x = __float2bfloat16(f2 - __bfloat162float(h23.x));
        l23.y = __float2bfloat16(f3 - __bfloat162float(h23.y));
        uint2 hp, lp;
        hp.x = *(uint32_t*)&h01; hp.y = *(uint32_t*)&h23;
        lp.x = *(uint32_t*)&l01; lp.y = *(uint32_t*)&l23;
        *(uint2*)&Ah[j] = hp;
        *(uint2*)&Al[j] = lp;
    }
}

// ============================================================
// K5: attn out via mma.sync — out[b,i,c] = x[b,i,c] + sum_j A[i,j]*S[j,c]
// CTA 128x128, 8 warps (64x32 tile), K = 3 segs x 1024 = 96 chunks of 32.
// ============================================================
__global__ __launch_bounds__(256) void k_av_mma(const float* __restrict__ x,
                                                float* __restrict__ out) {
    __shared__ __align__(16) char smbuf[32768];
    uint32_t smem_base = smem_u32(smbuf);
    const int tid = threadIdx.x, lane = tid & 31, wid = tid >> 5;
    const int wm = wid >> 2, wn = wid & 3;
    const int bb = blockIdx.z, i0 = blockIdx.y * 128, n0 = blockIdx.x * 128;

    float acc[4][4][4];
#pragma unroll
    for (int a = 0; a < 4; a++)
#pragma unroll
        for (int b = 0; b < 4; b++)
#pragma unroll
            for (int c = 0; c < 4; c++) acc[a][b][c] = 0.f;

    auto issue = [&](int kc, int buf) {
        int seg = kc >> 5, jc = (kc & 31) << 5;
        const __nv_bfloat16* Ap = (seg < 2 ? g_Ahi : g_Alo)
                                  + (size_t)(bb * HW + i0) * HW + jc;
        const __nv_bfloat16* Bp = (seg == 1 ? g_sTlo : g_sThi)
                                  + (size_t)(bb * CC + n0) * HW + jc;
        uint32_t Ab = smem_base + buf * 16384;
        uint32_t Bb = Ab + 8192;
#pragma unroll
        for (int u = 0; u < 2; u++) {
            int idx = tid + u * 256;
            int r = idx >> 2, c = idx & 3;
            uint32_t sw = (uint32_t)((c ^ ((r >> 1) & 3)) << 4);
            CP_ASYNC16(Ab + r * 64 + sw, Ap + (size_t)r * HW + c * 8);
            CP_ASYNC16(Bb + r * 64 + sw, Bp + (size_t)r * HW + c * 8);
        }
        CP_COMMIT();
    };

    const int NC = 96;
    issue(0, 0);
    for (int kc = 0; kc < NC; kc++) {
        if (kc + 1 < NC) { issue(kc + 1, (kc + 1) & 1); CP_WAIT1(); }
        else CP_WAIT0();
        __syncthreads();
        uint32_t Ab = smem_base + (kc & 1) * 16384;
        uint32_t Bb = Ab + 8192;
#pragma unroll
        for (int s = 0; s < 2; s++) {
            uint32_t afr[4][4];
#pragma unroll
            for (int mi = 0; mi < 4; mi++) {
                int r = wm * 64 + mi * 16 + (lane & 15);
                uint32_t addr = Ab + r * 64 + (((s*2 + (lane >> 4)) ^ ((r >> 1) & 3)) << 4);
                LDSM_X4(afr[mi][0], afr[mi][1], afr[mi][2], afr[mi][3], addr);
            }
            uint32_t bfr[2][4];
#pragma unroll
            for (int p = 0; p < 2; p++) {
                int nloc = p * 16 + ((lane >> 4) << 3) + (lane & 7);
                int khalf = (lane >> 3) & 1;
                int r = wn * 32 + nloc;
                uint32_t addr = Bb + r * 64 + (((s*2 + khalf) ^ ((r >> 1) & 3)) << 4);
                LDSM_X4(bfr[p][0], bfr[p][1], bfr[p][2], bfr[p][3], addr);
            }
#pragma unroll
            for (int mi = 0; mi < 4; mi++)
#pragma unroll
                for (int ni = 0; ni < 4; ni++)
                    MMA16816(acc[mi][ni], afr[mi],
                             bfr[ni >> 1][(ni & 1) * 2], bfr[ni >> 1][(ni & 1) * 2 + 1]);
        }
        __syncthreads();
    }

    // epilogue: + x residual
    int r0 = i0 + wm * 64 + (lane >> 2);
    int c0 = n0 + wn * 32 + (lane & 3) * 2;
#pragma unroll
    for (int mi = 0; mi < 4; mi++) {
#pragma unroll
        for (int ni = 0; ni < 4; ni++) {
            int gr = r0 + mi * 16;
            int gc = c0 + ni * 8;
            size_t o1 = ((size_t)bb * HW + gr) * CC + gc;
            float2 xv = *(const float2*)&x[o1];
            float2 ov;
            ov.x = acc[mi][ni][0] + xv.x;
            ov.y = acc[mi][ni][1] + xv.y;
            *(float2*)&out[o1] = ov;
            size_t o2 = o1 + (size_t)8 * CC;
            float2 xw = *(const float2*)&x[o2];
            float2 ow;
            ow.x = acc[mi][ni][2] + xw.x;
            ow.y = acc[mi][ni][3] + xw.y;
            *(float2*)&out[o2] = ow;
        }
    }
}

// ============================================================
extern "C" void kernel_launch(void* const* d_in, const int* in_sizes, int n_in,
                              void* d_out, int out_size) {
    (void)in_sizes; (void)n_in; (void)out_size;
    const float* x     = (const float*)d_in[0];
    const float* embW  = (const float*)d_in[1];
    const float* embb  = (const float*)d_in[2];
    const float* attnW = (const float*)d_in[3];
    const float* attnb = (const float*)d_in[4];
    const float* thrW  = (const float*)d_in[5];
    const float* thrb  = (const float*)d_in[6];
    float* out = (float*)d_out;

    k_emb<<<NROWS / 128, 256>>>(x, embW, embb);
    k_shortcut<<<dim3(CC / 128, NROWS / 128), 256>>>(x, attnW, attnb);
    k_thr<<<NROWS / 8, 256>>>(thrW, thrb);
    k_split<<<dim3(HW / 32, CC / 32, BB), 256>>>();
    k_gram_mma<<<dim3(HW / 128, HW / 128, BB), 256>>>();
    k_softmax<<<NROWS / 8, 256>>>();
    k_av_mma<<<dim3(CC / 128, HW / 128, BB), 256>>>(x, out);
}